// round 6
// baseline (speedup 1.0000x reference)
#include <cuda_runtime.h>
#include <cuda_fp16.h>
#include <cstdint>
#include <math.h>

// ============================================================================
// VisionExperts via mma.sync (HMMA fp16, f32 accum), single-product GEMM.
// Round 6: 128x256 CTA tiles (warp tile 64x64, 4 HMMA/LDSM), 3-stage cp.async
// pipeline with ONE barrier per K-chunk; side-stream prep overlap via events.
// ============================================================================

// ---------------- scratch (device globals; no allocs) ----------------
__device__ float g_gate[3 * 64];
__device__ float g_x336[21676032];
__device__ float g_feat[28311552];
__device__ __align__(128) __half g_A1_0[41943040];   // 65536 x 640
__device__ __align__(128) __half g_A1_1[23592960];   // 36864 x 640
__device__ __align__(128) __half g_A1_2[38535168];   // 12544 x 3072
__device__ __align__(128) __half g_A2[75497472];     // 65536 x 1152 (max)
__device__ __align__(128) __half g_Bt0[655360];      // 1024 x 640
__device__ __align__(128) __half g_Bp0[1048576];     // 1024 x 1024
__device__ __align__(128) __half g_Bt1[491520];      // 768 x 640
__device__ __align__(128) __half g_Bp1[786432];      // 1024 x 768
__device__ __align__(128) __half g_Bt2[3932160];     // 1280 x 3072 (N padded)
__device__ __align__(128) __half g_Bp2[1179648];     // 1024 x 1152

// ---------------- helpers ----------------
__device__ __forceinline__ uint32_t smem_u32(const void* p) {
    uint32_t a;
    asm("{ .reg .u64 t; cvta.to.shared.u64 t, %1; cvt.u32.u64 %0, t; }" : "=r"(a) : "l"(p));
    return a;
}
__device__ __forceinline__ void cp16(uint32_t so, const void* g) {
    asm volatile("cp.async.cg.shared.global [%0], [%1], 16;" :: "r"(so), "l"(g));
}
__device__ __forceinline__ void ldm4(uint32_t* r, uint32_t addr) {
    asm volatile("ldmatrix.sync.aligned.m8n8.x4.shared.b16 {%0,%1,%2,%3}, [%4];"
                 : "=r"(r[0]), "=r"(r[1]), "=r"(r[2]), "=r"(r[3]) : "r"(addr));
}
__device__ __forceinline__ void mma_f16(float* d, const uint32_t* a, uint32_t b0, uint32_t b1) {
    asm volatile("mma.sync.aligned.m16n8k16.row.col.f32.f16.f16.f32 "
                 "{%0,%1,%2,%3}, {%4,%5,%6,%7}, {%8,%9}, {%0,%1,%2,%3};"
                 : "+f"(d[0]), "+f"(d[1]), "+f"(d[2]), "+f"(d[3])
                 : "r"(a[0]), "r"(a[1]), "r"(a[2]), "r"(a[3]), "r"(b0), "r"(b1));
}

// ---------------- gates ----------------
__global__ void gate_kernel(const int* __restrict__ sel, const float* __restrict__ rw) {
    int b = threadIdx.x;
    if (b >= 64) return;
    float w0 = 0.f, w1 = 0.f, w2 = 0.f;
#pragma unroll
    for (int k = 0; k < 2; k++) {
        int e = sel[b * 2 + k];
        float r = rw[b * 2 + k];
        w0 += (e == 0) ? r : 0.f;
        w1 += (e == 1) ? r : 0.f;
        w2 += (e == 2) ? r : 0.f;
    }
    g_gate[b] = w0; g_gate[64 + b] = w1; g_gate[128 + b] = w2;
}

// ---------------- input resize 448 -> 336 ----------------
__global__ void resize_input_kernel(const float* __restrict__ x) {
    long long idx = (long long)blockIdx.x * blockDim.x + threadIdx.x;
    const long long total = 64LL * 3 * 336 * 336;
    if (idx >= total) return;
    int ox = (int)(idx % 336);
    long long r = idx / 336;
    int oy = (int)(r % 336); r /= 336;
    int c = (int)(r % 3);
    int b = (int)(r / 3);
    if (g_gate[64 + b] == 0.f) return;
    const float sc = 447.0f / 335.0f;
    float ys = oy * sc, xs = ox * sc;
    int y0 = (int)floorf(ys); int y1 = min(y0 + 1, 447);
    int x0 = (int)floorf(xs); int x1 = min(x0 + 1, 447);
    float ty = ys - (float)y0, tx = xs - (float)x0;
    const float* p = x + ((long long)(b * 3 + c)) * 448 * 448;
    float a = p[y0 * 448 + x0], bv = p[y0 * 448 + x1];
    float cv = p[y1 * 448 + x0], dv = p[y1 * 448 + x1];
    float r0 = a * (1.f - ty) + cv * ty;
    float r1 = bv * (1.f - ty) + dv * ty;
    g_x336[idx] = r0 * (1.f - tx) + r1 * tx;
}

// ---------------- weight transpose: W[K,Nreal] -> B[Npad,Kp] fp16 ----------
__global__ void weight_halfT(const float* __restrict__ W, int K, int Nreal, int Kp, int Npad,
                             __half* __restrict__ B) {
    long long idx = (long long)blockIdx.x * blockDim.x + threadIdx.x;
    long long total = (long long)Npad * Kp;
    if (idx >= total) return;
    int k = (int)(idx % Kp);
    int n = (int)(idx / Kp);
    float v = (k < K && n < Nreal) ? W[(long long)k * Nreal + n] : 0.f;
    B[idx] = __float2half_rn(v);
}

// ---------------- im2col -> fp16 (templated; 8 elems/thread) ----------------
template <int S, int P, int G, int KP>
__global__ void im2col_half(const float* __restrict__ src, const float* __restrict__ gate,
                            __half* __restrict__ A) {
    constexpr int K = 3 * P * P;
    constexpr int GG = G * G;
    long long v8 = (long long)blockIdx.x * blockDim.x + threadIdx.x;
    const long long total8 = 64LL * GG * (KP / 8);
    if (v8 >= total8) return;
    int kc = (int)(v8 % (KP / 8));
    long long row = v8 / (KP / 8);
    int t = (int)(row % GG);
    int b = (int)(row / GG);
    if (gate[b] == 0.f) return;
    const int ty = t / G, tx = t % G;
    const float* sb = src + ((long long)b * 3) * S * S;
    __half h[8];
#pragma unroll
    for (int j = 0; j < 8; j++) {
        int k = kc * 8 + j;
        float v = 0.f;
        if (k < K) {
            int ch = k / (P * P);
            int rr = k - ch * (P * P);
            int py = rr / P, px = rr - py * P;
            v = sb[((long long)ch * S + (ty * P + py)) * S + (tx * P + px)];
        }
        h[j] = __float2half_rn(v);
    }
    *reinterpret_cast<uint4*>(&A[row * KP + kc * 8]) = *reinterpret_cast<uint4*>(h);
}

// ---------------- grid resize g->32 -> fp16 (templated; 8 ch/thread) --------
template <int G, int C>
__global__ void resize_grid_half(const float* __restrict__ feat, const float* __restrict__ gate,
                                 __half* __restrict__ A) {
    long long v8 = (long long)blockIdx.x * blockDim.x + threadIdx.x;
    const long long total8 = 64LL * 1024 * (C / 8);
    if (v8 >= total8) return;
    int cc = (int)(v8 % (C / 8));
    long long r = v8 / (C / 8);
    int ot = (int)(r % 1024);
    int b = (int)(r / 1024);
    if (gate[b] == 0.f) return;
    int oy = ot >> 5, ox = ot & 31;
    const float sc = (float)(G - 1) / 31.0f;
    float ys = oy * sc, xs = ox * sc;
    int y0 = (int)floorf(ys); int y1 = min(y0 + 1, G - 1);
    int x0 = (int)floorf(xs); int x1 = min(x0 + 1, G - 1);
    float ty = ys - (float)y0, tx = xs - (float)x0;
    const float* fb = feat + (long long)b * G * G * C + cc * 8;
    const float* p00 = fb + (long long)(y0 * G + x0) * C;
    const float* p01 = fb + (long long)(y0 * G + x1) * C;
    const float* p10 = fb + (long long)(y1 * G + x0) * C;
    const float* p11 = fb + (long long)(y1 * G + x1) * C;
    __half h[8];
#pragma unroll
    for (int j = 0; j < 8; j += 4) {
        float4 a = *reinterpret_cast<const float4*>(p00 + j);
        float4 bv = *reinterpret_cast<const float4*>(p01 + j);
        float4 cv = *reinterpret_cast<const float4*>(p10 + j);
        float4 dv = *reinterpret_cast<const float4*>(p11 + j);
        float r0, r1;
        r0 = a.x * (1.f - ty) + cv.x * ty; r1 = bv.x * (1.f - ty) + dv.x * ty;
        h[j + 0] = __float2half_rn(r0 * (1.f - tx) + r1 * tx);
        r0 = a.y * (1.f - ty) + cv.y * ty; r1 = bv.y * (1.f - ty) + dv.y * ty;
        h[j + 1] = __float2half_rn(r0 * (1.f - tx) + r1 * tx);
        r0 = a.z * (1.f - ty) + cv.z * ty; r1 = bv.z * (1.f - ty) + dv.z * ty;
        h[j + 2] = __float2half_rn(r0 * (1.f - tx) + r1 * tx);
        r0 = a.w * (1.f - ty) + cv.w * ty; r1 = bv.w * (1.f - ty) + dv.w * ty;
        h[j + 3] = __float2half_rn(r0 * (1.f - tx) + r1 * tx);
    }
    *reinterpret_cast<uint4*>(&A[((long long)(b * 1024 + ot)) * C + cc * 8]) =
        *reinterpret_cast<uint4*>(h);
}

// ---------------- HMMA GEMM: C = A @ B^T, fp32 accumulate ------------------
// CTA tile 128x256, warp tile 64x64 (2x4 warps). K-chunk 64, 3-stage pipeline,
// one __syncthreads per chunk.
// outmode 0: outF = acc + bias      1: outF += gate*(acc+bias)      2: outH
// Store guarded by col < Nout (N may be padded to mult of 256 for B).
__global__ void __launch_bounds__(256) gemm_mma(
    const __half* __restrict__ A, const __half* __restrict__ B,
    const float* __restrict__ bias, int Nout, int Kp,
    const float* __restrict__ gate, int gg, int outmode,
    float* __restrict__ outF, __half* __restrict__ outH)
{
    const int row0 = blockIdx.y * 128;
    const int col0 = blockIdx.x * 256;
    {   // gated tile skip
        int b0 = row0 / gg, b1 = (row0 + 127) / gg;
        float gm = 0.f;
        for (int b = b0; b <= b1; b++) gm = fmaxf(gm, gate[b]);
        if (gm == 0.f) return;
    }

    extern __shared__ char smem[];
    const uint32_t S = smem_u32(smem);
    const int tid = threadIdx.x;
    const int wid = tid >> 5, lane = tid & 31;
    const int wm = (wid >> 2) * 64;     // warp m offset (2 rows)
    const int wn = (wid & 3) * 64;      // warp n offset (4 cols)
    const int NC = Kp >> 6;

    // stage (48KB): A 128rows x 128B (16KB) | B 256rows x 128B (32KB)
    auto prefetch = [&](int c) {
        uint32_t st = S + (uint32_t)(c % 3) * 49152u;
        int kt = c << 6;
#pragma unroll
        for (int i = 0; i < 12; i++) {
            int cid = tid + (i << 8);
            if (cid < 1024) {
                int r = cid >> 3, j = cid & 7;
                cp16(st + r * 128 + ((j ^ (r & 7)) << 4),
                     A + (size_t)(row0 + r) * Kp + kt + j * 8);
            } else {
                int bc = cid - 1024;
                int r = bc >> 3, j = bc & 7;
                cp16(st + 16384u + r * 128 + ((j ^ (r & 7)) << 4),
                     B + (size_t)(col0 + r) * Kp + kt + j * 8);
            }
        }
        asm volatile("cp.async.commit_group;" ::: "memory");
    };

    float acc[4][8][4];
#pragma unroll
    for (int i = 0; i < 4; i++)
#pragma unroll
        for (int j = 0; j < 8; j++)
#pragma unroll
            for (int q = 0; q < 4; q++) acc[i][j][q] = 0.f;

    const int lrow = lane & 15;
    const int lchunk = lane >> 4;

    prefetch(0);
    if (NC > 1) prefetch(1);
    for (int c = 0; c < NC; c++) {
        if (c + 1 < NC) {
            asm volatile("cp.async.wait_group 1;" ::: "memory");
        } else {
            asm volatile("cp.async.wait_group 0;" ::: "memory");
        }
        __syncthreads();

        uint32_t SA = S + (uint32_t)(c % 3) * 49152u;
        uint32_t SB = SA + 16384u;

#pragma unroll
        for (int k = 0; k < 4; k++) {
            const int ch = 2 * k + lchunk;
            uint32_t b[4][4];
#pragma unroll
            for (int j2 = 0; j2 < 4; j2++) {
                int rb = wn + j2 * 16 + lrow;
                ldm4(b[j2], SB + rb * 128 + ((ch ^ (rb & 7)) << 4));
            }
#pragma unroll
            for (int i = 0; i < 4; i++) {
                int ra = wm + i * 16 + lrow;
                uint32_t a[4];
                ldm4(a, SA + ra * 128 + ((ch ^ (ra & 7)) << 4));
#pragma unroll
                for (int j2 = 0; j2 < 4; j2++) {
                    mma_f16(acc[i][2 * j2],     a, b[j2][0], b[j2][2]);
                    mma_f16(acc[i][2 * j2 + 1], a, b[j2][1], b[j2][3]);
                }
            }
        }
        if (c + 2 < NC) prefetch(c + 2);
    }

    // ---- epilogue ----
    const int grp = lane >> 2, qid = lane & 3;
#pragma unroll
    for (int i = 0; i < 4; i++) {
        int r0 = row0 + wm + i * 16 + grp;
        int r1 = r0 + 8;
        float w0 = 0.f, w1 = 0.f;
        if (outmode == 1) { w0 = gate[r0 / gg]; w1 = gate[r1 / gg]; }
#pragma unroll
        for (int j = 0; j < 8; j++) {
            int col = col0 + wn + j * 8 + qid * 2;
            if (col >= Nout) continue;
            float b0 = bias[col], b1 = bias[col + 1];
            float v00 = acc[i][j][0] + b0, v01 = acc[i][j][1] + b1;
            float v10 = acc[i][j][2] + b0, v11 = acc[i][j][3] + b1;
            if (outmode == 0) {
                *reinterpret_cast<float2*>(&outF[(size_t)r0 * Nout + col]) = make_float2(v00, v01);
                *reinterpret_cast<float2*>(&outF[(size_t)r1 * Nout + col]) = make_float2(v10, v11);
            } else if (outmode == 1) {
                if (w0 != 0.f) {
                    float2 o = *reinterpret_cast<const float2*>(&outF[(size_t)r0 * Nout + col]);
                    o.x += w0 * v00; o.y += w0 * v01;
                    *reinterpret_cast<float2*>(&outF[(size_t)r0 * Nout + col]) = o;
                }
                if (w1 != 0.f) {
                    float2 o = *reinterpret_cast<const float2*>(&outF[(size_t)r1 * Nout + col]);
                    o.x += w1 * v10; o.y += w1 * v11;
                    *reinterpret_cast<float2*>(&outF[(size_t)r1 * Nout + col]) = o;
                }
            } else {
                __half2 hp;
                hp.x = __float2half_rn(v00); hp.y = __float2half_rn(v01);
                *reinterpret_cast<__half2*>(&outH[(size_t)r0 * Nout + col]) = hp;
                hp.x = __float2half_rn(v10); hp.y = __float2half_rn(v11);
                *reinterpret_cast<__half2*>(&outH[(size_t)r1 * Nout + col]) = hp;
            }
        }
    }
}

// ---------------- launch ----------------
static inline int nblk(long long total, int t) { return (int)((total + t - 1) / t); }

extern "C" void kernel_launch(void* const* d_in, const int* in_sizes, int n_in,
                              void* d_out, int out_size) {
    const float* x   = (const float*)d_in[0];
    const int*   sel = (const int*)d_in[1];
    const float* rw  = (const float*)d_in[2];
    const float* wt0 = (const float*)d_in[3];  const float* bt0 = (const float*)d_in[4];
    const float* wp0 = (const float*)d_in[5];  const float* bp0 = (const float*)d_in[6];
    const float* wt1 = (const float*)d_in[7];  const float* bt1 = (const float*)d_in[8];
    const float* wp1 = (const float*)d_in[9];  const float* bp1 = (const float*)d_in[10];
    const float* wt2 = (const float*)d_in[11]; const float* bt2 = (const float*)d_in[12];
    const float* wp2 = (const float*)d_in[13]; const float* bp2 = (const float*)d_in[14];
    float* out = (float*)d_out;

    float *gate_d, *x336_d, *feat_d;
    __half *A10, *A11, *A12, *A2, *Bt0, *Bp0, *Bt1, *Bp1, *Bt2, *Bp2;
    cudaGetSymbolAddress((void**)&gate_d, g_gate);
    cudaGetSymbolAddress((void**)&x336_d, g_x336);
    cudaGetSymbolAddress((void**)&feat_d, g_feat);
    cudaGetSymbolAddress((void**)&A10, g_A1_0);
    cudaGetSymbolAddress((void**)&A11, g_A1_1);
    cudaGetSymbolAddress((void**)&A12, g_A1_2);
    cudaGetSymbolAddress((void**)&A2, g_A2);
    cudaGetSymbolAddress((void**)&Bt0, g_Bt0);
    cudaGetSymbolAddress((void**)&Bp0, g_Bp0);
    cudaGetSymbolAddress((void**)&Bt1, g_Bt1);
    cudaGetSymbolAddress((void**)&Bp1, g_Bp1);
    cudaGetSymbolAddress((void**)&Bt2, g_Bt2);
    cudaGetSymbolAddress((void**)&Bp2, g_Bp2);

    static cudaStream_t s1 = nullptr;
    static cudaEvent_t evG = nullptr, evB0 = nullptr, evS1 = nullptr;
    if (s1 == nullptr) {
        cudaStreamCreateWithFlags(&s1, cudaStreamNonBlocking);
        cudaEventCreateWithFlags(&evG, cudaEventDisableTiming);
        cudaEventCreateWithFlags(&evB0, cudaEventDisableTiming);
        cudaEventCreateWithFlags(&evS1, cudaEventDisableTiming);
    }

    const int SMEM = 3 * 49152;
    cudaFuncSetAttribute(gemm_mma, cudaFuncAttributeMaxDynamicSharedMemorySize, SMEM);

    // ---- main: gates, then fork side stream ----
    gate_kernel<<<1, 64>>>(sel, rw);
    cudaEventRecord(evG, 0);
    cudaMemsetAsync(d_out, 0, (size_t)out_size * sizeof(float));

    // ---- side stream: all weight transposes + e1/e2 A-prep ----
    cudaStreamWaitEvent(s1, evG, 0);
    weight_halfT<<<nblk(1024LL * 640, 256), 256, 0, s1>>>(wt0, 588, 1024, 640, 1024, Bt0);
    weight_halfT<<<nblk(1024LL * 1024, 256), 256, 0, s1>>>(wp0, 1024, 1024, 1024, 1024, Bp0);
    cudaEventRecord(evB0, s1);
    weight_halfT<<<nblk(768LL * 640, 256), 256, 0, s1>>>(wt1, 588, 768, 640, 768, Bt1);
    weight_halfT<<<nblk(1024LL * 768, 256), 256, 0, s1>>>(wp1, 768, 1024, 768, 1024, Bp1);
    weight_halfT<<<nblk(1280LL * 3072, 256), 256, 0, s1>>>(wt2, 3072, 1152, 3072, 1280, Bt2);
    weight_halfT<<<nblk(1024LL * 1152, 256), 256, 0, s1>>>(wp2, 1152, 1024, 1152, 1024, Bp2);
    resize_input_kernel<<<nblk(64LL * 3 * 336 * 336, 256), 256, 0, s1>>>(x);
    im2col_half<336, 14, 24, 640><<<nblk(64LL * 576 * 80, 256), 256, 0, s1>>>(x336_d, gate_d + 64, A11);
    im2col_half<448, 32, 14, 3072><<<nblk(64LL * 196 * 384, 256), 256, 0, s1>>>(x, gate_d + 128, A12);
    cudaEventRecord(evS1, s1);

    // ---- main: expert 0 ----
    im2col_half<448, 14, 32, 640><<<nblk(64LL * 1024 * 80, 256), 256>>>(x, gate_d, A10);
    cudaStreamWaitEvent(0, evB0, 0);
    gemm_mma<<<dim3(4, 512), 256, SMEM>>>(A10, Bt0, bt0, 1024, 640, gate_d, 1024, 2, nullptr, A2);
    gemm_mma<<<dim3(4, 512), 256, SMEM>>>(A2, Bp0, bp0, 1024, 1024, gate_d, 1024, 1, out, nullptr);

    // ---- main: expert 1 (join side stream) ----
    cudaStreamWaitEvent(0, evS1, 0);
    gemm_mma<<<dim3(3, 288), 256, SMEM>>>(A11, Bt1, bt1, 768, 640, gate_d + 64, 576, 0, feat_d, nullptr);
    resize_grid_half<24, 768><<<nblk(64LL * 1024 * 96, 256), 256>>>(feat_d, gate_d + 64, A2);
    gemm_mma<<<dim3(4, 512), 256, SMEM>>>(A2, Bp1, bp1, 1024, 768, gate_d + 64, 1024, 1, out, nullptr);

    // ---- main: expert 2 ----
    gemm_mma<<<dim3(5, 98), 256, SMEM>>>(A12, Bt2, bt2, 1152, 3072, gate_d + 128, 196, 0, feat_d, nullptr);
    resize_grid_half<14, 1152><<<nblk(64LL * 1024 * 144, 256), 256>>>(feat_d, gate_d + 128, A2);
    gemm_mma<<<dim3(4, 512), 256, SMEM>>>(A2, Bp2, bp2, 1024, 1152, gate_d + 128, 1024, 1, out, nullptr);
}

// round 7
// speedup vs baseline: 1.4101x; 1.4101x over previous
#include <cuda_runtime.h>
#include <cuda_fp16.h>
#include <cstdint>
#include <math.h>

// ============================================================================
// VisionExperts via mma.sync (HMMA fp16, f32 accum), single-product GEMM.
// Round 7: R5-proven GEMM (128x128 CTA, 64x32 warp tile, 3-stage cp.async)
// + two-stream DAG overlap with per-expert buffers. Projectors serialized
// (RMW into out); towers/resizes of e1/e2 overlap e0's GEMM chain.
// ============================================================================

// ---------------- scratch (device globals; no allocs) ----------------
__device__ float g_gate[3 * 64];
__device__ float g_x336[21676032];
__device__ float g_feat1[28311552];                  // e1 tower out (36864x768)
__device__ float g_feat2[14450688];                  // e2 tower out (12544x1152)
__device__ __align__(128) __half g_A1_0[41943040];   // 65536 x 640
__device__ __align__(128) __half g_A1_1[23592960];   // 36864 x 640
__device__ __align__(128) __half g_A1_2[38535168];   // 12544 x 3072
__device__ __align__(128) __half g_A2_0[67108864];   // 65536 x 1024
__device__ __align__(128) __half g_A2_1[50331648];   // 65536 x 768
__device__ __align__(128) __half g_A2_2[75497472];   // 65536 x 1152
__device__ __align__(128) __half g_Bt0[655360];      // 1024 x 640
__device__ __align__(128) __half g_Bp0[1048576];     // 1024 x 1024
__device__ __align__(128) __half g_Bt1[491520];      // 768 x 640
__device__ __align__(128) __half g_Bp1[786432];      // 1024 x 768
__device__ __align__(128) __half g_Bt2[3538944];     // 1152 x 3072
__device__ __align__(128) __half g_Bp2[1179648];     // 1024 x 1152

// ---------------- helpers ----------------
__device__ __forceinline__ uint32_t smem_u32(const void* p) {
    uint32_t a;
    asm("{ .reg .u64 t; cvta.to.shared.u64 t, %1; cvt.u32.u64 %0, t; }" : "=r"(a) : "l"(p));
    return a;
}
__device__ __forceinline__ void cp16(uint32_t so, const void* g) {
    asm volatile("cp.async.cg.shared.global [%0], [%1], 16;" :: "r"(so), "l"(g));
}
__device__ __forceinline__ void ldm4(uint32_t* r, uint32_t addr) {
    asm volatile("ldmatrix.sync.aligned.m8n8.x4.shared.b16 {%0,%1,%2,%3}, [%4];"
                 : "=r"(r[0]), "=r"(r[1]), "=r"(r[2]), "=r"(r[3]) : "r"(addr));
}
__device__ __forceinline__ void mma_f16(float* d, const uint32_t* a, uint32_t b0, uint32_t b1) {
    asm volatile("mma.sync.aligned.m16n8k16.row.col.f32.f16.f16.f32 "
                 "{%0,%1,%2,%3}, {%4,%5,%6,%7}, {%8,%9}, {%0,%1,%2,%3};"
                 : "+f"(d[0]), "+f"(d[1]), "+f"(d[2]), "+f"(d[3])
                 : "r"(a[0]), "r"(a[1]), "r"(a[2]), "r"(a[3]), "r"(b0), "r"(b1));
}

// ---------------- gates ----------------
__global__ void gate_kernel(const int* __restrict__ sel, const float* __restrict__ rw) {
    int b = threadIdx.x;
    if (b >= 64) return;
    float w0 = 0.f, w1 = 0.f, w2 = 0.f;
#pragma unroll
    for (int k = 0; k < 2; k++) {
        int e = sel[b * 2 + k];
        float r = rw[b * 2 + k];
        w0 += (e == 0) ? r : 0.f;
        w1 += (e == 1) ? r : 0.f;
        w2 += (e == 2) ? r : 0.f;
    }
    g_gate[b] = w0; g_gate[64 + b] = w1; g_gate[128 + b] = w2;
}

// ---------------- input resize 448 -> 336 ----------------
__global__ void resize_input_kernel(const float* __restrict__ x) {
    long long idx = (long long)blockIdx.x * blockDim.x + threadIdx.x;
    const long long total = 64LL * 3 * 336 * 336;
    if (idx >= total) return;
    int ox = (int)(idx % 336);
    long long r = idx / 336;
    int oy = (int)(r % 336); r /= 336;
    int c = (int)(r % 3);
    int b = (int)(r / 3);
    if (g_gate[64 + b] == 0.f) return;
    const float sc = 447.0f / 335.0f;
    float ys = oy * sc, xs = ox * sc;
    int y0 = (int)floorf(ys); int y1 = min(y0 + 1, 447);
    int x0 = (int)floorf(xs); int x1 = min(x0 + 1, 447);
    float ty = ys - (float)y0, tx = xs - (float)x0;
    const float* p = x + ((long long)(b * 3 + c)) * 448 * 448;
    float a = p[y0 * 448 + x0], bv = p[y0 * 448 + x1];
    float cv = p[y1 * 448 + x0], dv = p[y1 * 448 + x1];
    float r0 = a * (1.f - ty) + cv * ty;
    float r1 = bv * (1.f - ty) + dv * ty;
    g_x336[idx] = r0 * (1.f - tx) + r1 * tx;
}

// ---------------- weight transpose: W[K,N] -> B[N,Kp] fp16 ----------------
__global__ void weight_halfT(const float* __restrict__ W, int K, int N, int Kp,
                             __half* __restrict__ B) {
    long long idx = (long long)blockIdx.x * blockDim.x + threadIdx.x;
    long long total = (long long)N * Kp;
    if (idx >= total) return;
    int k = (int)(idx % Kp);
    int n = (int)(idx / Kp);
    float v = (k < K) ? W[(long long)k * N + n] : 0.f;
    B[idx] = __float2half_rn(v);
}

// ---------------- im2col -> fp16 (templated; 8 elems/thread) ----------------
template <int S, int P, int G, int KP>
__global__ void im2col_half(const float* __restrict__ src, const float* __restrict__ gate,
                            __half* __restrict__ A) {
    constexpr int K = 3 * P * P;
    constexpr int GG = G * G;
    long long v8 = (long long)blockIdx.x * blockDim.x + threadIdx.x;
    const long long total8 = 64LL * GG * (KP / 8);
    if (v8 >= total8) return;
    int kc = (int)(v8 % (KP / 8));
    long long row = v8 / (KP / 8);
    int t = (int)(row % GG);
    int b = (int)(row / GG);
    if (gate[b] == 0.f) return;
    const int ty = t / G, tx = t % G;
    const float* sb = src + ((long long)b * 3) * S * S;
    __half h[8];
#pragma unroll
    for (int j = 0; j < 8; j++) {
        int k = kc * 8 + j;
        float v = 0.f;
        if (k < K) {
            int ch = k / (P * P);
            int rr = k - ch * (P * P);
            int py = rr / P, px = rr - py * P;
            v = sb[((long long)ch * S + (ty * P + py)) * S + (tx * P + px)];
        }
        h[j] = __float2half_rn(v);
    }
    *reinterpret_cast<uint4*>(&A[row * KP + kc * 8]) = *reinterpret_cast<uint4*>(h);
}

// ---------------- grid resize g->32 -> fp16 (templated; 8 ch/thread) --------
template <int G, int C>
__global__ void resize_grid_half(const float* __restrict__ feat, const float* __restrict__ gate,
                                 __half* __restrict__ A) {
    long long v8 = (long long)blockIdx.x * blockDim.x + threadIdx.x;
    const long long total8 = 64LL * 1024 * (C / 8);
    if (v8 >= total8) return;
    int cc = (int)(v8 % (C / 8));
    long long r = v8 / (C / 8);
    int ot = (int)(r % 1024);
    int b = (int)(r / 1024);
    if (gate[b] == 0.f) return;
    int oy = ot >> 5, ox = ot & 31;
    const float sc = (float)(G - 1) / 31.0f;
    float ys = oy * sc, xs = ox * sc;
    int y0 = (int)floorf(ys); int y1 = min(y0 + 1, G - 1);
    int x0 = (int)floorf(xs); int x1 = min(x0 + 1, G - 1);
    float ty = ys - (float)y0, tx = xs - (float)x0;
    const float* fb = feat + (long long)b * G * G * C + cc * 8;
    const float* p00 = fb + (long long)(y0 * G + x0) * C;
    const float* p01 = fb + (long long)(y0 * G + x1) * C;
    const float* p10 = fb + (long long)(y1 * G + x0) * C;
    const float* p11 = fb + (long long)(y1 * G + x1) * C;
    __half h[8];
#pragma unroll
    for (int j = 0; j < 8; j += 4) {
        float4 a = *reinterpret_cast<const float4*>(p00 + j);
        float4 bv = *reinterpret_cast<const float4*>(p01 + j);
        float4 cv = *reinterpret_cast<const float4*>(p10 + j);
        float4 dv = *reinterpret_cast<const float4*>(p11 + j);
        float r0, r1;
        r0 = a.x * (1.f - ty) + cv.x * ty; r1 = bv.x * (1.f - ty) + dv.x * ty;
        h[j + 0] = __float2half_rn(r0 * (1.f - tx) + r1 * tx);
        r0 = a.y * (1.f - ty) + cv.y * ty; r1 = bv.y * (1.f - ty) + dv.y * ty;
        h[j + 1] = __float2half_rn(r0 * (1.f - tx) + r1 * tx);
        r0 = a.z * (1.f - ty) + cv.z * ty; r1 = bv.z * (1.f - ty) + dv.z * ty;
        h[j + 2] = __float2half_rn(r0 * (1.f - tx) + r1 * tx);
        r0 = a.w * (1.f - ty) + cv.w * ty; r1 = bv.w * (1.f - ty) + dv.w * ty;
        h[j + 3] = __float2half_rn(r0 * (1.f - tx) + r1 * tx);
    }
    *reinterpret_cast<uint4*>(&A[((long long)(b * 1024 + ot)) * C + cc * 8]) =
        *reinterpret_cast<uint4*>(h);
}

// ---------------- HMMA GEMM (R5-proven): C = A @ B^T, fp32 accumulate ------
// 128x128 CTA tile, warp tile 64x32, K-chunk 64, 3-stage cp.async pipeline.
// outmode 0: outF = acc + bias   1: outF += gate*(acc+bias)   2: outH
__global__ void __launch_bounds__(256) gemm_mma(
    const __half* __restrict__ A, const __half* __restrict__ B,
    const float* __restrict__ bias, int N, int Kp,
    const float* __restrict__ gate, int gg, int outmode,
    float* __restrict__ outF, __half* __restrict__ outH)
{
    const int row0 = blockIdx.y * 128;
    const int col0 = blockIdx.x * 128;
    {   // gated tile skip
        int b0 = row0 / gg, b1 = (row0 + 127) / gg;
        float gm = 0.f;
        for (int b = b0; b <= b1; b++) gm = fmaxf(gm, gate[b]);
        if (gm == 0.f) return;
    }

    extern __shared__ char smem[];
    const uint32_t S = smem_u32(smem);
    const int tid = threadIdx.x;
    const int wid = tid >> 5, lane = tid & 31;
    const int wm = (wid >> 2) * 64;
    const int wn = (wid & 3) * 32;
    const int NC = Kp >> 6;

    auto prefetch = [&](int c) {
        uint32_t st = S + (uint32_t)(c % 3) * 32768u;
        int kt = c << 6;
#pragma unroll
        for (int i = 0; i < 8; i++) {
            int cid = tid + (i << 8);
            int isB = cid >> 10;
            int rem = cid & 1023;
            int r = rem >> 3, j = rem & 7;
            const __half* gp = (!isB ? A + (size_t)(row0 + r) * Kp
                                     : B + (size_t)(col0 + r) * Kp) + kt + j * 8;
            uint32_t so = st + (isB << 14) + r * 128 + ((j ^ (r & 7)) << 4);
            cp16(so, gp);
        }
        asm volatile("cp.async.commit_group;" ::: "memory");
    };

    float acc[4][4][4];
#pragma unroll
    for (int i = 0; i < 4; i++)
#pragma unroll
        for (int j = 0; j < 4; j++)
#pragma unroll
            for (int q = 0; q < 4; q++) acc[i][j][q] = 0.f;

    const int lrow = lane & 15;
    const int lchunk = lane >> 4;

    prefetch(0);
    if (NC > 1) prefetch(1);
    for (int c = 0; c < NC; c++) {
        if (c + 2 < NC) {
            prefetch(c + 2);
            asm volatile("cp.async.wait_group 2;" ::: "memory");
        } else if (c + 1 < NC) {
            asm volatile("cp.async.wait_group 1;" ::: "memory");
        } else {
            asm volatile("cp.async.wait_group 0;" ::: "memory");
        }
        __syncthreads();

        uint32_t SA = S + (uint32_t)(c % 3) * 32768u;
        uint32_t SB = SA + 16384u;

#pragma unroll
        for (int k = 0; k < 4; k++) {
            const int ch = 2 * k + lchunk;
            uint32_t b[2][4];
#pragma unroll
            for (int j2 = 0; j2 < 2; j2++) {
                int rb = wn + j2 * 16 + lrow;
                ldm4(b[j2], SB + rb * 128 + ((ch ^ (rb & 7)) << 4));
            }
#pragma unroll
            for (int i = 0; i < 4; i++) {
                int ra = wm + i * 16 + lrow;
                uint32_t a[4];
                ldm4(a, SA + ra * 128 + ((ch ^ (ra & 7)) << 4));
#pragma unroll
                for (int j2 = 0; j2 < 2; j2++) {
                    mma_f16(acc[i][2 * j2],     a, b[j2][0], b[j2][2]);
                    mma_f16(acc[i][2 * j2 + 1], a, b[j2][1], b[j2][3]);
                }
            }
        }
        __syncthreads();
    }

    // ---- epilogue ----
    const int grp = lane >> 2, qid = lane & 3;
#pragma unroll
    for (int i = 0; i < 4; i++) {
        int r0 = row0 + wm + i * 16 + grp;
        int r1 = r0 + 8;
#pragma unroll
        for (int j = 0; j < 4; j++) {
            int col = col0 + wn + j * 8 + qid * 2;
            float b0 = bias[col], b1 = bias[col + 1];
            float v00 = acc[i][j][0] + b0, v01 = acc[i][j][1] + b1;
            float v10 = acc[i][j][2] + b0, v11 = acc[i][j][3] + b1;
            if (outmode == 0) {
                *reinterpret_cast<float2*>(&outF[(size_t)r0 * N + col]) = make_float2(v00, v01);
                *reinterpret_cast<float2*>(&outF[(size_t)r1 * N + col]) = make_float2(v10, v11);
            } else if (outmode == 1) {
                float w0 = gate[r0 / gg], w1 = gate[r1 / gg];
                if (w0 != 0.f) {
                    float2 o = *reinterpret_cast<const float2*>(&outF[(size_t)r0 * N + col]);
                    o.x += w0 * v00; o.y += w0 * v01;
                    *reinterpret_cast<float2*>(&outF[(size_t)r0 * N + col]) = o;
                }
                if (w1 != 0.f) {
                    float2 o = *reinterpret_cast<const float2*>(&outF[(size_t)r1 * N + col]);
                    o.x += w1 * v10; o.y += w1 * v11;
                    *reinterpret_cast<float2*>(&outF[(size_t)r1 * N + col]) = o;
                }
            } else {
                __half2 hp;
                hp.x = __float2half_rn(v00); hp.y = __float2half_rn(v01);
                *reinterpret_cast<__half2*>(&outH[(size_t)r0 * N + col]) = hp;
                hp.x = __float2half_rn(v10); hp.y = __float2half_rn(v11);
                *reinterpret_cast<__half2*>(&outH[(size_t)r1 * N + col]) = hp;
            }
        }
    }
}

// ---------------- launch ----------------
static inline int nblk(long long total, int t) { return (int)((total + t - 1) / t); }

extern "C" void kernel_launch(void* const* d_in, const int* in_sizes, int n_in,
                              void* d_out, int out_size) {
    const float* x   = (const float*)d_in[0];
    const int*   sel = (const int*)d_in[1];
    const float* rw  = (const float*)d_in[2];
    const float* wt0 = (const float*)d_in[3];  const float* bt0 = (const float*)d_in[4];
    const float* wp0 = (const float*)d_in[5];  const float* bp0 = (const float*)d_in[6];
    const float* wt1 = (const float*)d_in[7];  const float* bt1 = (const float*)d_in[8];
    const float* wp1 = (const float*)d_in[9];  const float* bp1 = (const float*)d_in[10];
    const float* wt2 = (const float*)d_in[11]; const float* bt2 = (const float*)d_in[12];
    const float* wp2 = (const float*)d_in[13]; const float* bp2 = (const float*)d_in[14];
    float* out = (float*)d_out;

    float *gate_d, *x336_d, *feat1_d, *feat2_d;
    __half *A10, *A11, *A12, *A20, *A21, *A22, *Bt0, *Bp0, *Bt1, *Bp1, *Bt2, *Bp2;
    cudaGetSymbolAddress((void**)&gate_d, g_gate);
    cudaGetSymbolAddress((void**)&x336_d, g_x336);
    cudaGetSymbolAddress((void**)&feat1_d, g_feat1);
    cudaGetSymbolAddress((void**)&feat2_d, g_feat2);
    cudaGetSymbolAddress((void**)&A10, g_A1_0);
    cudaGetSymbolAddress((void**)&A11, g_A1_1);
    cudaGetSymbolAddress((void**)&A12, g_A1_2);
    cudaGetSymbolAddress((void**)&A20, g_A2_0);
    cudaGetSymbolAddress((void**)&A21, g_A2_1);
    cudaGetSymbolAddress((void**)&A22, g_A2_2);
    cudaGetSymbolAddress((void**)&Bt0, g_Bt0);
    cudaGetSymbolAddress((void**)&Bp0, g_Bp0);
    cudaGetSymbolAddress((void**)&Bt1, g_Bt1);
    cudaGetSymbolAddress((void**)&Bp1, g_Bp1);
    cudaGetSymbolAddress((void**)&Bt2, g_Bt2);
    cudaGetSymbolAddress((void**)&Bp2, g_Bp2);

    static cudaStream_t s1 = nullptr;
    static cudaEvent_t evG = nullptr, evB0 = nullptr, evRG1 = nullptr, evRG2 = nullptr;
    if (s1 == nullptr) {
        cudaStreamCreateWithFlags(&s1, cudaStreamNonBlocking);
        cudaEventCreateWithFlags(&evG, cudaEventDisableTiming);
        cudaEventCreateWithFlags(&evB0, cudaEventDisableTiming);
        cudaEventCreateWithFlags(&evRG1, cudaEventDisableTiming);
        cudaEventCreateWithFlags(&evRG2, cudaEventDisableTiming);
    }

    const int SMEM = 3 * 32768;
    cudaFuncSetAttribute(gemm_mma, cudaFuncAttributeMaxDynamicSharedMemorySize, SMEM);

    // ---- main: gates, memset; fork side stream ----
    gate_kernel<<<1, 64>>>(sel, rw);
    cudaEventRecord(evG, 0);
    cudaMemsetAsync(d_out, 0, (size_t)out_size * sizeof(float));

    // ---- side stream: weights + e1/e2 full tower pipelines ----
    cudaStreamWaitEvent(s1, evG, 0);
    weight_halfT<<<nblk(1024LL * 640, 256), 256, 0, s1>>>(wt0, 588, 1024, 640, Bt0);
    weight_halfT<<<nblk(1024LL * 1024, 256), 256, 0, s1>>>(wp0, 1024, 1024, 1024, Bp0);
    cudaEventRecord(evB0, s1);
    weight_halfT<<<nblk(768LL * 640, 256), 256, 0, s1>>>(wt1, 588, 768, 640, Bt1);
    weight_halfT<<<nblk(1024LL * 768, 256), 256, 0, s1>>>(wp1, 768, 1024, 768, Bp1);
    weight_halfT<<<nblk(1152LL * 3072, 256), 256, 0, s1>>>(wt2, 3072, 1152, 3072, Bt2);
    weight_halfT<<<nblk(1024LL * 1152, 256), 256, 0, s1>>>(wp2, 1152, 1024, 1152, Bp2);
    resize_input_kernel<<<nblk(64LL * 3 * 336 * 336, 256), 256, 0, s1>>>(x);
    im2col_half<336, 14, 24, 640><<<nblk(64LL * 576 * 80, 256), 256, 0, s1>>>(x336_d, gate_d + 64, A11);
    gemm_mma<<<dim3(6, 288), 256, SMEM, s1>>>(A11, Bt1, bt1, 768, 640,
                                              gate_d + 64, 576, 0, feat1_d, nullptr);
    resize_grid_half<24, 768><<<nblk(64LL * 1024 * 96, 256), 256, 0, s1>>>(feat1_d, gate_d + 64, A21);
    cudaEventRecord(evRG1, s1);
    im2col_half<448, 32, 14, 3072><<<nblk(64LL * 196 * 384, 256), 256, 0, s1>>>(x, gate_d + 128, A12);
    gemm_mma<<<dim3(9, 98), 256, SMEM, s1>>>(A12, Bt2, bt2, 1152, 3072,
                                             gate_d + 128, 196, 0, feat2_d, nullptr);
    resize_grid_half<14, 1152><<<nblk(64LL * 1024 * 144, 256), 256, 0, s1>>>(feat2_d, gate_d + 128, A22);
    cudaEventRecord(evRG2, s1);

    // ---- main: expert 0 chain, then serialized projectors ----
    im2col_half<448, 14, 32, 640><<<nblk(64LL * 1024 * 80, 256), 256>>>(x, gate_d, A10);
    cudaStreamWaitEvent(0, evB0, 0);
    gemm_mma<<<dim3(8, 512), 256, SMEM>>>(A10, Bt0, bt0, 1024, 640, gate_d, 1024, 2, nullptr, A20);
    gemm_mma<<<dim3(8, 512), 256, SMEM>>>(A20, Bp0, bp0, 1024, 1024, gate_d, 1024, 1, out, nullptr);
    cudaStreamWaitEvent(0, evRG1, 0);
    gemm_mma<<<dim3(8, 512), 256, SMEM>>>(A21, Bp1, bp1, 1024, 768, gate_d + 64, 1024, 1, out, nullptr);
    cudaStreamWaitEvent(0, evRG2, 0);
    gemm_mma<<<dim3(8, 512), 256, SMEM>>>(A22, Bp2, bp2, 1024, 1152, gate_d + 128, 1024, 1, out, nullptr);
}